// round 1
// baseline (speedup 1.0000x reference)
#include <cuda_runtime.h>
#include <cuda_bf16.h>

// GMM log-likelihood, N=524288, K=32, D=8.
// Inputs: d_in[0]=x [N,8] f32, d_in[1]=pi [32] f32, d_in[2]=means [32,8] f32,
//         d_in[3]=chol_var [32,8,8] f32. Output: [N] f32.
//
// Strategy:
//  prep kernel (1 warp): per component k build L=tril(chol), cov=LL^T+eps I,
//    C=chol(cov), Cinv (tri inverse), fold -0.5 via 1/sqrt(2) scaling, fold
//    logdet + D*log2pi + log_softmax(pi) into one constant. Params stored
//    PRE-PACKED as (k, k+16) float2 pairs so the main kernel's fma.rn.f32x2
//    reads them directly from shared memory with no broadcast MOVs.
//  main kernel: each thread = 2 points; per k-pair: 45 FFMA2 (tri matvec with
//    -zm folded as addend, squared-norm accum, const - q). Then 32-way
//    logsumexp per point with __expf (MUFU, cheap at this instruction count).

typedef unsigned long long u64;

#define NPTS 524288
#define KCOMP 32
#define KP 16            // k-pairs
#define DIM 8
#define PSTRIDE 48       // padded params per k-pair (45 used)
#define NPARAM 45

__device__ __align__(16) float g_w[KP * PSTRIDE * 2];  // (kp, m, lane) lane=0 -> k=kp, lane=1 -> k=kp+16

// ---------------- packed f32x2 helpers ----------------
__device__ __forceinline__ u64 pack2(float a, float b) {
    u64 r; asm("mov.b64 %0, {%1, %2};" : "=l"(r) : "f"(a), "f"(b)); return r;
}
__device__ __forceinline__ float lo2(u64 v) {
    float a; asm("{ .reg .f32 t; mov.b64 {%0, t}, %1; }" : "=f"(a) : "l"(v)); return a;
}
__device__ __forceinline__ float hi2(u64 v) {
    float b; asm("{ .reg .f32 t; mov.b64 {t, %0}, %1; }" : "=f"(b) : "l"(v)); return b;
}
__device__ __forceinline__ u64 ffma2(u64 a, u64 b, u64 c) {
    u64 d; asm("fma.rn.f32x2 %0, %1, %2, %3;" : "=l"(d) : "l"(a), "l"(b), "l"(c)); return d;
}

// ---------------- precompute kernel (32 threads) ----------------
__global__ void gmm_prep(const float* __restrict__ pi,
                         const float* __restrict__ means,
                         const float* __restrict__ cv) {
    int k = threadIdx.x;
    if (k >= KCOMP) return;

    float L[DIM][DIM];
    for (int i = 0; i < DIM; i++)
        for (int j = 0; j < DIM; j++)
            L[i][j] = (j <= i) ? cv[k * 64 + i * 8 + j] : 0.0f;

    float cov[DIM][DIM];
    for (int i = 0; i < DIM; i++)
        for (int j = 0; j <= i; j++) {
            float s = 0.0f;
            for (int p = 0; p < DIM; p++) s += L[i][p] * L[j][p];
            cov[i][j] = s;
        }
    for (int i = 0; i < DIM; i++) cov[i][i] += 1e-6f;

    // Cholesky (lower) of cov
    float C[DIM][DIM];
    for (int j = 0; j < DIM; j++) {
        float d = cov[j][j];
        for (int p = 0; p < j; p++) d -= C[j][p] * C[j][p];
        C[j][j] = sqrtf(d);
        for (int i = j + 1; i < DIM; i++) {
            float t = cov[i][j];
            for (int p = 0; p < j; p++) t -= C[i][p] * C[j][p];
            C[i][j] = t / C[j][j];
        }
    }
    float logdet = 0.0f;
    for (int j = 0; j < DIM; j++) logdet += logf(C[j][j]);
    logdet *= 2.0f;

    // Inverse of lower-triangular C
    float Ci[DIM][DIM];
    for (int c = 0; c < DIM; c++) {
        Ci[c][c] = 1.0f / C[c][c];
        for (int i = c + 1; i < DIM; i++) {
            float t = 0.0f;
            for (int p = c; p < i; p++) t += C[i][p] * Ci[p][c];
            Ci[i][c] = -t / C[i][i];
        }
    }

    float zm[DIM];
    for (int i = 0; i < DIM; i++) {
        float t = 0.0f;
        for (int j = 0; j <= i; j++) t += Ci[i][j] * means[k * 8 + j];
        zm[i] = t;
    }

    // log_softmax(pi)[k] via warp reduction (exactly 32 lanes)
    float pk = pi[k];
    float mx = pk;
    for (int o = 16; o; o >>= 1) mx = fmaxf(mx, __shfl_xor_sync(0xffffffffu, mx, o));
    float se = expf(pk - mx);
    for (int o = 16; o; o >>= 1) se += __shfl_xor_sync(0xffffffffu, se, o);
    float lp = pk - mx - logf(se);

    const float LOG_2PI = 1.8378770664093453f;
    float cst = lp - 0.5f * (8.0f * LOG_2PI + logdet);

    const float s = 0.70710678118654752f;  // 1/sqrt(2): folds the -0.5 into ||.||^2
    int kp = k & (KP - 1);
    int lane = k >> 4;

    int idx = 0;
    for (int i = 0; i < DIM; i++)
        for (int j = 0; j <= i; j++) {
            g_w[(kp * PSTRIDE + idx) * 2 + lane] = Ci[i][j] * s;
            idx++;
        }
    for (int i = 0; i < DIM; i++)
        g_w[(kp * PSTRIDE + 36 + i) * 2 + lane] = -zm[i] * s;
    g_w[(kp * PSTRIDE + 44) * 2 + lane] = cst;
}

// ---------------- logsumexp over 32 stored values ----------------
__device__ __forceinline__ float lse32(const u64* wl) {
    float v[32];
#pragma unroll
    for (int i = 0; i < 16; i++) { v[2 * i] = lo2(wl[i]); v[2 * i + 1] = hi2(wl[i]); }
    // 4 parallel max chains
    float m0 = v[0], m1 = v[1], m2 = v[2], m3 = v[3];
#pragma unroll
    for (int i = 4; i < 32; i += 4) {
        m0 = fmaxf(m0, v[i]); m1 = fmaxf(m1, v[i + 1]);
        m2 = fmaxf(m2, v[i + 2]); m3 = fmaxf(m3, v[i + 3]);
    }
    float m = fmaxf(fmaxf(m0, m1), fmaxf(m2, m3));
    float s0 = 0.f, s1 = 0.f, s2 = 0.f, s3 = 0.f;
#pragma unroll
    for (int i = 0; i < 32; i += 4) {
        s0 += __expf(v[i] - m);
        s1 += __expf(v[i + 1] - m);
        s2 += __expf(v[i + 2] - m);
        s3 += __expf(v[i + 3] - m);
    }
    return m + __logf((s0 + s1) + (s2 + s3));
}

// ---------------- main kernel ----------------
__global__ void __launch_bounds__(256) gmm_main(const float* __restrict__ x,
                                                float* __restrict__ out,
                                                int half) {
    __shared__ __align__(16) u64 sw[KP * PSTRIDE];

    // cooperative param load (6 KB)
    {
        const float4* g4 = reinterpret_cast<const float4*>(g_w);
        float4* s4 = reinterpret_cast<float4*>(sw);
        const int n4 = KP * PSTRIDE * 2 / 4;  // 384
        for (int i = threadIdx.x; i < n4; i += blockDim.x) s4[i] = g4[i];
    }
    __syncthreads();

    int gid = blockIdx.x * blockDim.x + threadIdx.x;
    if (gid >= half) return;

    // two points per thread: gid and gid+half (both coalesced float4 loads)
    const float4* xa4 = reinterpret_cast<const float4*>(x + (size_t)gid * 8);
    const float4* xb4 = reinterpret_cast<const float4*>(x + ((size_t)gid + (size_t)half) * 8);
    float4 a0 = xa4[0], a1 = xa4[1];
    float4 b0 = xb4[0], b1 = xb4[1];

    u64 xa[8], xb[8];
    xa[0] = pack2(a0.x, a0.x); xa[1] = pack2(a0.y, a0.y);
    xa[2] = pack2(a0.z, a0.z); xa[3] = pack2(a0.w, a0.w);
    xa[4] = pack2(a1.x, a1.x); xa[5] = pack2(a1.y, a1.y);
    xa[6] = pack2(a1.z, a1.z); xa[7] = pack2(a1.w, a1.w);
    xb[0] = pack2(b0.x, b0.x); xb[1] = pack2(b0.y, b0.y);
    xb[2] = pack2(b0.z, b0.z); xb[3] = pack2(b0.w, b0.w);
    xb[4] = pack2(b1.x, b1.x); xb[5] = pack2(b1.y, b1.y);
    xb[6] = pack2(b1.z, b1.z); xb[7] = pack2(b1.w, b1.w);

    const u64 negone = pack2(-1.0f, -1.0f);

    u64 wa[KP], wb[KP];

#pragma unroll
    for (int kp = 0; kp < KP; kp++) {
        const u64* w = sw + kp * PSTRIDE;
        u64 qa = 0ull, qb = 0ull;
        int idx = 0;
#pragma unroll
        for (int i = 0; i < DIM; i++) {
            u64 zi = w[36 + i];   // -zm_i/sqrt(2) packed for (k, k+16)
            u64 za = zi, zb = zi;
#pragma unroll
            for (int j = 0; j <= i; j++) {
                u64 p = w[idx];   // Cinv[i][j]/sqrt(2) packed
                idx++;
                za = ffma2(p, xa[j], za);
                zb = ffma2(p, xb[j], zb);
            }
            qa = ffma2(za, za, qa);
            qb = ffma2(zb, zb, qb);
        }
        u64 c = w[44];            // const (logdet + log2pi + log_softmax term)
        wa[kp] = ffma2(qa, negone, c);   // wll = c - q
        wb[kp] = ffma2(qb, negone, c);
    }

    out[gid] = lse32(wa);
    out[gid + half] = lse32(wb);
}

extern "C" void kernel_launch(void* const* d_in, const int* in_sizes, int n_in,
                              void* d_out, int out_size) {
    const float* x     = (const float*)d_in[0];
    const float* pi    = (const float*)d_in[1];
    const float* means = (const float*)d_in[2];
    const float* cv    = (const float*)d_in[3];
    float* out = (float*)d_out;

    const int n    = in_sizes[0] / 8;   // 524288
    const int half = n / 2;             // 262144

    gmm_prep<<<1, 32>>>(pi, means, cv);
    gmm_main<<<half / 256, 256>>>(x, out, half);
}

// round 2
// speedup vs baseline: 1.2036x; 1.2036x over previous
#include <cuda_runtime.h>

// GMM log-likelihood, N=524288, K=32, D=8. Single fused kernel.
//
// Math: cov = LL^T + eps*I with eps=1e-6. We use L directly instead of
// recomputing chol(cov): any sign flips between L and the true Cholesky
// factor leave maha = ||L^{-1}x - L^{-1}mu||^2 and logdet = 2*sum(log|L_ii|)
// invariant, and the eps*I perturbation is ~1e-6 relative (<< 1e-3 tol).
//
// Params packed as (k, k+16) float2 pairs in smem, in exact consumption
// order so the unrolled main loop reads them as LDS.128. Per point-k:
// fma.rn.f32x2 triangular matvec with -L^{-1}mu folded as addend, squared
// norm, then streaming exp-accumulate against a precomputed upper bound
// M = max_k c_k (no stored wll array, no deferred max -> low registers).

typedef unsigned long long u64;

#define DIM 8
#define KP 16          // k-pairs (k, k+16)
#define SLOTS 46       // u64 slots per k-pair (45 used, padded even for LDS.128)

// ---------------- packed f32x2 helpers ----------------
__device__ __forceinline__ u64 pack2(float a, float b) {
    u64 r; asm("mov.b64 %0, {%1, %2};" : "=l"(r) : "f"(a), "f"(b)); return r;
}
__device__ __forceinline__ void unpack2(u64 v, float& a, float& b) {
    asm("mov.b64 {%0, %1}, %2;" : "=f"(a), "=f"(b) : "l"(v));
}
__device__ __forceinline__ u64 ffma2(u64 a, u64 b, u64 c) {
    u64 d; asm("fma.rn.f32x2 %0, %1, %2, %3;" : "=l"(d) : "l"(a), "l"(b), "l"(c)); return d;
}

// slot layout per k-pair (consumption order of the main loop):
//   for i in 0..7:  z_i  then  p_i0..p_ii     (8 + 36 slots)
//   then c' at slot 44                          (45 total, slot 45 pad)
__device__ __forceinline__ int slot_z(int i) { return i + (i * (i + 1)) / 2; }
__device__ __forceinline__ int slot_p(int i, int j) { return i + (i * (i + 1)) / 2 + 1 + j; }

__global__ void __launch_bounds__(256, 4)
gmm_fused(const float* __restrict__ x,
          const float* __restrict__ pi,
          const float* __restrict__ means,
          const float* __restrict__ cv,
          float* __restrict__ out, int half) {
    __shared__ __align__(16) u64 sw[KP * SLOTS];
    __shared__ float sM;

    const int tid = threadIdx.x;
    const int gid = blockIdx.x * blockDim.x + tid;

    // issue x loads early; they overlap warp 0's prep work
    const float4* xa4 = reinterpret_cast<const float4*>(x + (size_t)gid * 8);
    const float4* xb4 = reinterpret_cast<const float4*>(x + ((size_t)gid + (size_t)half) * 8);
    float4 a0 = xa4[0], a1 = xa4[1];
    float4 b0 = xb4[0], b1 = xb4[1];

    // ---------------- prep: warp 0, one thread per component ----------------
    if (tid < 32) {
        const int k = tid;
        const int kp = k & (KP - 1);
        const int lane = k >> 4;
        float* swf = reinterpret_cast<float*>(sw);

        // L lower-triangular, packed idx(i,j) = i(i+1)/2 + j
        float L[36];
#pragma unroll
        for (int i = 0; i < DIM; i++)
#pragma unroll
            for (int j = 0; j <= i; j++)
                L[(i * (i + 1)) / 2 + j] = cv[k * 64 + i * 8 + j];

        float Ld[DIM];  // 1/L_ii
#pragma unroll
        for (int i = 0; i < DIM; i++)
            Ld[i] = __fdividef(1.0f, L[(i * (i + 1)) / 2 + i]);

        float mu[DIM];
#pragma unroll
        for (int j = 0; j < DIM; j++) mu[j] = means[k * 8 + j];

        const float s = 0.70710678118654752f;  // 1/sqrt(2) folds the -0.5
        float zm[DIM];
#pragma unroll
        for (int i = 0; i < DIM; i++) zm[i] = 0.0f;

        // triangular inverse, column by column; write scaled entries,
        // accumulate zm_i = sum_j w_ij * mu_j on the fly
#pragma unroll
        for (int c = 0; c < DIM; c++) {
            float g[DIM];
            g[c] = Ld[c];
#pragma unroll
            for (int i = c + 1; i < DIM; i++) {
                float t = 0.0f;
#pragma unroll
                for (int p = c; p < i; p++) t += L[(i * (i + 1)) / 2 + p] * g[p];
                g[i] = -t * Ld[i];
            }
#pragma unroll
            for (int i = c; i < DIM; i++) {
                float wv = g[i] * s;
                swf[(kp * SLOTS + slot_p(i, c)) * 2 + lane] = wv;
                zm[i] += wv * mu[c];
            }
        }
#pragma unroll
        for (int i = 0; i < DIM; i++)
            swf[(kp * SLOTS + slot_z(i)) * 2 + lane] = -zm[i];

        // logdet = 2 * sum log|L_ii|
        float logdet = 0.0f;
#pragma unroll
        for (int i = 0; i < DIM; i++)
            logdet += __logf(fabsf(L[(i * (i + 1)) / 2 + i]));
        logdet *= 2.0f;

        // log_softmax(pi)[k] across the 32 lanes
        float pk = pi[k];
        float mx = pk;
#pragma unroll
        for (int o = 16; o; o >>= 1) mx = fmaxf(mx, __shfl_xor_sync(0xffffffffu, mx, o));
        float se = __expf(pk - mx);
#pragma unroll
        for (int o = 16; o; o >>= 1) se += __shfl_xor_sync(0xffffffffu, se, o);
        float lp = pk - mx - __logf(se);

        const float LOG_2PI = 1.8378770664093453f;
        float cst = lp - 0.5f * (8.0f * LOG_2PI + logdet);

        // M = max_k cst; fold into constant
        float M = cst;
#pragma unroll
        for (int o = 16; o; o >>= 1) M = fmaxf(M, __shfl_xor_sync(0xffffffffu, M, o));
        swf[(kp * SLOTS + 44) * 2 + lane] = cst - M;
        if (k == 0) sM = M;
    }
    __syncthreads();

    // ---------------- main loop ----------------
    u64 xp[DIM], xq[DIM];
    xp[0] = pack2(a0.x, a0.x); xp[1] = pack2(a0.y, a0.y);
    xp[2] = pack2(a0.z, a0.z); xp[3] = pack2(a0.w, a0.w);
    xp[4] = pack2(a1.x, a1.x); xp[5] = pack2(a1.y, a1.y);
    xp[6] = pack2(a1.z, a1.z); xp[7] = pack2(a1.w, a1.w);
    xq[0] = pack2(b0.x, b0.x); xq[1] = pack2(b0.y, b0.y);
    xq[2] = pack2(b0.z, b0.z); xq[3] = pack2(b0.w, b0.w);
    xq[4] = pack2(b1.x, b1.x); xq[5] = pack2(b1.y, b1.y);
    xq[6] = pack2(b1.z, b1.z); xq[7] = pack2(b1.w, b1.w);

    const u64 negone = pack2(-1.0f, -1.0f);
    float sa0 = 0.f, sa1 = 0.f, sb0 = 0.f, sb1 = 0.f;

#define NEXT(dst) do { if ((pos & 1) == 0) { tt = w2[pos >> 1]; (dst) = tt.x; } \
                       else (dst) = tt.y; pos++; } while (0)

#pragma unroll
    for (int kp = 0; kp < KP; kp++) {
        const ulonglong2* w2 = reinterpret_cast<const ulonglong2*>(sw) + kp * (SLOTS / 2);
        ulonglong2 tt;
        int pos = 0;
        u64 qa = 0ull, qb = 0ull;
#pragma unroll
        for (int i = 0; i < DIM; i++) {
            u64 zi; NEXT(zi);
            u64 za = zi, zb = zi;
#pragma unroll
            for (int j = 0; j <= i; j++) {
                u64 p; NEXT(p);
                za = ffma2(p, xp[j], za);
                zb = ffma2(p, xq[j], zb);
            }
            qa = ffma2(za, za, qa);
            qb = ffma2(zb, zb, qb);
        }
        u64 cc; NEXT(cc);
        u64 wa = ffma2(qa, negone, cc);   // c' - q  (already offset by -M)
        u64 wb = ffma2(qb, negone, cc);
        float f0, f1;
        unpack2(wa, f0, f1);
        sa0 += __expf(f0); sa1 += __expf(f1);
        unpack2(wb, f0, f1);
        sb0 += __expf(f0); sb1 += __expf(f1);
    }
#undef NEXT

    const float M = sM;
    out[gid] = M + __logf(fmaxf(sa0 + sa1, 1e-37f));
    out[gid + (size_t)half] = M + __logf(fmaxf(sb0 + sb1, 1e-37f));
}

extern "C" void kernel_launch(void* const* d_in, const int* in_sizes, int n_in,
                              void* d_out, int out_size) {
    const float* x     = (const float*)d_in[0];
    const float* pi    = (const float*)d_in[1];
    const float* means = (const float*)d_in[2];
    const float* cv    = (const float*)d_in[3];
    float* out = (float*)d_out;

    const int n    = in_sizes[0] / 8;   // 524288
    const int half = n / 2;             // 262144

    gmm_fused<<<half / 256, 256>>>(x, pi, means, cv, out, half);
}